// round 10
// baseline (speedup 1.0000x reference)
#include <cuda_runtime.h>
#include <math.h>

#define N_NODES 50000
#define N_EDGES 800000
#define H 64
#define S 16
#define EF 16
#define ATT_W 144
#define UPD_W 128
#define CSR_BLOCKS 148
#define CSR_CH 338          // ceil(50000/148)

// ---------------- scratch (static device allocations) ----------------
__device__ float g_Psrc[N_NODES * ATT_W];
__device__ float g_Pdst[N_NODES * ATT_W];   // includes att_b1 folded in
__device__ float g_efw[(size_t)N_EDGES * ATT_W];  // per-edge ef projection (460MB)
__device__ float g_raw[N_EDGES];            // CSR-ordered raw scores
__device__ float g_agg[N_NODES * H];
__device__ int   g_deg[N_NODES];
__device__ int   g_rowptr[N_NODES + 1];
__device__ int   g_cursor[N_NODES];
__device__ int   g_es[N_EDGES];             // CSR-ordered original edge id
__device__ int   g_ss[N_EDGES];             // CSR-ordered src
__device__ int   g_ds[N_EDGES];             // CSR-ordered dst
__device__ int   g_bsum[CSR_BLOCKS];
__device__ unsigned int g_count;

// ---------------- f32x2 packed helpers ----------------
__device__ __forceinline__ unsigned long long pk2(float lo, float hi) {
    unsigned long long r;
    asm("mov.b64 %0, {%1, %2};" : "=l"(r) : "f"(lo), "f"(hi));
    return r;
}
__device__ __forceinline__ void upk2(unsigned long long v, float& lo, float& hi) {
    asm("mov.b64 {%0, %1}, %2;" : "=f"(lo), "=f"(hi) : "l"(v));
}
__device__ __forceinline__ unsigned long long ffma2(unsigned long long a,
                                                    unsigned long long b,
                                                    unsigned long long c) {
    unsigned long long d;
    asm("fma.rn.f32x2 %0, %1, %2, %3;" : "=l"(d) : "l"(a), "l"(b), "l"(c));
    return d;
}

// ---------------- CSR: reset then fused build ----------------
__global__ void csr_reset_kernel() {
    int i = blockIdx.x * blockDim.x + threadIdx.x;
    if (i < N_NODES) { g_deg[i] = 0; g_cursor[i] = 0; }
    if (i == 0) g_count = 0u;
}

__device__ __forceinline__ void gbar(int phase) {
    __syncthreads();
    if (threadIdx.x == 0) {
        __threadfence();
        atomicAdd(&g_count, 1u);
        while (*((volatile unsigned int*)&g_count) < (unsigned)(phase * CSR_BLOCKS)) { }
        __threadfence();
    }
    __syncthreads();
}

__global__ void __launch_bounds__(512) csr_build_kernel(const int* __restrict__ ei) {
    __shared__ int ssum[512];
    __shared__ int boff[CSR_BLOCKS];
    int t = threadIdx.x;
    int gid = blockIdx.x * 512 + t;

    // phase 1: degree histogram
    for (int e = gid; e < N_EDGES; e += CSR_BLOCKS * 512)
        atomicAdd(&g_deg[ei[N_EDGES + e]], 1);
    gbar(1);

    // phase 2: per-block inclusive scan of this block's node chunk
    int nbase = blockIdx.x * CSR_CH;
    int node = nbase + t;
    int dv = 0;
    if (t < CSR_CH && node < N_NODES) dv = g_deg[node];
    ssum[t] = dv;
    __syncthreads();
    for (int off = 1; off < 512; off <<= 1) {
        int v = (t >= off) ? ssum[t - off] : 0;
        __syncthreads();
        ssum[t] += v;
        __syncthreads();
    }
    int incl = ssum[t];
    if (t == 511) g_bsum[blockIdx.x] = ssum[511];
    gbar(2);

    // phase 3: exclusive scan of block sums, write rowptr
    if (t < CSR_BLOCKS) boff[t] = g_bsum[t];
    __syncthreads();
    if (t == 0) {
        int run = 0;
        for (int b = 0; b < CSR_BLOCKS; b++) { int tmp = boff[b]; boff[b] = run; run += tmp; }
    }
    __syncthreads();
    int myoff = boff[blockIdx.x];
    if (t < CSR_CH && node < N_NODES) g_rowptr[node] = myoff + incl - dv;
    if (blockIdx.x == 0 && t == 0) g_rowptr[N_NODES] = N_EDGES;
    gbar(3);

    // phase 4: fill (CSR-ordered edge id + src + dst)
    for (int e = gid; e < N_EDGES; e += CSR_BLOCKS * 512) {
        int s = ei[e];
        int d = ei[N_EDGES + e];
        int pos = g_rowptr[d] + atomicAdd(&g_cursor[d], 1);
        g_es[pos] = e;
        g_ss[pos] = s;
        g_ds[pos] = d;
    }
}

// ---------------- node projections (register-tiled GEMM) ----------------
// b1 is folded into the Pdst half.
__global__ void proj_kernel(const float* __restrict__ x,
                            const float* __restrict__ xs,
                            const float* __restrict__ w1,
                            const float* __restrict__ b1) {
    extern __shared__ float sm[];
    float* Wt = sm;                 // [f][j]: 80 x 288
    float* Xs = Wt + 80 * 288;      // [n][f]: 16 x 81 (pad)
    __shared__ float b1s[144];
    int tid = threadIdx.x;

    for (int idx = tid; idx < 80 * 288; idx += blockDim.x) {
        int j = idx % 288, f = idx / 288;
        int jr = (j < 144) ? j : j - 144;
        int col;
        if (j < 144) col = (f < 64) ? f : 64 + f;        // x[src] | xs[src]
        else         col = (f < 64) ? 64 + f : 80 + f;   // x[dst] | xs[dst]
        Wt[f * 288 + j] = w1[jr * 176 + col];
    }
    if (tid < 144) b1s[tid] = b1[tid];
    __syncthreads();

    int tj = tid >> 3;      // 0..35
    int tn = tid & 7;       // 0..7
    const int NCH = N_NODES / 16;   // 3125 exact

    for (int c = blockIdx.x; c < NCH; c += gridDim.x) {
        int n0 = c * 16;
        for (int idx = tid; idx < 16 * 80; idx += blockDim.x) {
            int n = idx / 80, f = idx % 80;
            int nd = n0 + n;
            Xs[n * 81 + f] = (f < 64) ? x[nd * 64 + f] : xs[nd * 16 + (f - 64)];
        }
        __syncthreads();

        float acc[8][2];
#pragma unroll
        for (int jj = 0; jj < 8; jj++) { acc[jj][0] = 0.f; acc[jj][1] = 0.f; }

        for (int f = 0; f < 80; f++) {
            float4 w0 = *(const float4*)&Wt[f * 288 + tj * 8];
            float4 w1v = *(const float4*)&Wt[f * 288 + tj * 8 + 4];
            float x0 = Xs[(tn * 2 + 0) * 81 + f];
            float x1 = Xs[(tn * 2 + 1) * 81 + f];
            float wv[8] = {w0.x, w0.y, w0.z, w0.w, w1v.x, w1v.y, w1v.z, w1v.w};
#pragma unroll
            for (int jj = 0; jj < 8; jj++) {
                acc[jj][0] = fmaf(wv[jj], x0, acc[jj][0]);
                acc[jj][1] = fmaf(wv[jj], x1, acc[jj][1]);
            }
        }

#pragma unroll
        for (int u = 0; u < 2; u++) {
            int nd = n0 + tn * 2 + u;
            int j = tj * 8;
            if (j < 144) {
                float4 o0 = {acc[0][u], acc[1][u], acc[2][u], acc[3][u]};
                float4 o1 = {acc[4][u], acc[5][u], acc[6][u], acc[7][u]};
                *(float4*)&g_Psrc[nd * 144 + j] = o0;
                *(float4*)&g_Psrc[nd * 144 + j + 4] = o1;
            } else {
                int jb = j - 144;
                float4 o0 = {acc[0][u] + b1s[jb + 0], acc[1][u] + b1s[jb + 1],
                             acc[2][u] + b1s[jb + 2], acc[3][u] + b1s[jb + 3]};
                float4 o1 = {acc[4][u] + b1s[jb + 4], acc[5][u] + b1s[jb + 5],
                             acc[6][u] + b1s[jb + 6], acc[7][u] + b1s[jb + 7]};
                *(float4*)&g_Pdst[nd * 144 + jb] = o0;
                *(float4*)&g_Pdst[nd * 144 + jb + 4] = o1;
            }
        }
        __syncthreads();
    }
}

// ---------------- edge-feature projection GEMM: g_efw[e][j] = ef[e] @ We^T ----------
// Original edge order (fully coalesced). 288 threads = 4 edge-slots x 72 threads;
// each thread owns 2 adjacent outputs (j0, j0+1), We pairs in 16 ULL registers.
__global__ void __launch_bounds__(288, 4) efproj_kernel(
        const float* __restrict__ ef, const float* __restrict__ w1) {
    __shared__ __align__(16) float efs[4][16];
    int tid = threadIdx.x;
    int slot = tid / 72;            // 0..3 (tid<288)
    int lt = tid % 72;
    int j0 = lt * 2;                // 0,2,...,142

    unsigned long long wp0[8], wp1[8];
#pragma unroll
    for (int fp = 0; fp < 8; fp++) {
        wp0[fp] = pk2(w1[j0 * 176 + 160 + 2 * fp], w1[j0 * 176 + 160 + 2 * fp + 1]);
        wp1[fp] = pk2(w1[(j0 + 1) * 176 + 160 + 2 * fp], w1[(j0 + 1) * 176 + 160 + 2 * fp + 1]);
    }

    for (int e0 = blockIdx.x * 4; e0 < N_EDGES; e0 += gridDim.x * 4) {
        __syncthreads();
        if (tid < 16)
            ((float4*)&efs[0][0])[tid] = ((const float4*)(ef + (size_t)e0 * 16))[tid];
        __syncthreads();

        int e = e0 + slot;
        if (e < N_EDGES) {
            const unsigned long long* ep = (const unsigned long long*)&efs[slot][0];
            unsigned long long a0 = pk2(0.f, 0.f), a1 = pk2(0.f, 0.f);
#pragma unroll
            for (int fp = 0; fp < 8; fp++) {
                unsigned long long v = ep[fp];
                a0 = ffma2(v, wp0[fp], a0);
                a1 = ffma2(v, wp1[fp], a1);
            }
            float l0, h0, l1, h1;
            upk2(a0, l0, h0); upk2(a1, l1, h1);
            float2 o = make_float2(l0 + h0, l1 + h1);
            *(float2*)&g_efw[(size_t)e * 144 + j0] = o;   // coalesced 576B per edge
        }
    }
}

// ---------------- edge score kernel: pure gather-reduce ----------------
// warp per CSR chunk; per edge: 15 predicated single-line LDGs + relu-dot.
// Partials parked in smem; transpose-sum per 32 edges.
__global__ void __launch_bounds__(128, 8) score_kernel(
        const float* __restrict__ w2, const float* __restrict__ b2) {
    __shared__ float part[4][32 * 33];
    int tid = threadIdx.x;
    int lane = tid & 31;
    int wip = tid >> 5;
    float* myPart = part[wip];

    float w2r[5];
#pragma unroll
    for (int k = 0; k < 5; k++) {
        int j = lane + 32 * k;
        w2r[k] = (j < 144) ? w2[j] : 0.f;
    }
    float b2v = b2[0];

    int gw = (blockIdx.x * blockDim.x + tid) >> 5;
    int nw = (gridDim.x * blockDim.x) >> 5;
    int chunk = (N_EDGES + nw - 1) / nw;
    int p0 = gw * chunk;
    int p1 = min(p0 + chunk, N_EDGES);

    for (int cb = p0; cb < p1; cb += 32) {
        int cd = min(32, p1 - cb);      // warp-uniform

        int myS = (lane < cd) ? g_ss[cb + lane] : 0;
        int myD = (lane < cd) ? g_ds[cb + lane] : 0;
        int myE = (lane < cd) ? g_es[cb + lane] : 0;

#pragma unroll 4
        for (int t = 0; t < cd; t++) {
            int s = __shfl_sync(0xffffffffu, myS, t);
            int d = __shfl_sync(0xffffffffu, myD, t);
            int e = __shfl_sync(0xffffffffu, myE, t);

            const float* psrow = &g_Psrc[(size_t)s * 144];
            const float* pdrow = &g_Pdst[(size_t)d * 144];
            const float* ewrow = &g_efw[(size_t)e * 144];

            float p = 0.f;
#pragma unroll
            for (int k = 0; k < 5; k++) {
                int j = lane + 32 * k;
                if (j < 144) {
                    float h = psrow[j] + pdrow[j] + ewrow[j];   // b1 folded into Pdst
                    p = fmaf(fmaxf(h, 0.f), w2r[k], p);
                }
            }
            myPart[t * 33 + lane] = p;   // STS ends the chain
        }
        __syncwarp();

        // transpose-sum: lane t sums row t (conflict-free: bank=(t+i)&31)
        if (lane < cd) {
            const float* row = &myPart[lane * 33];
            float s0 = 0.f, s1 = 0.f, s2 = 0.f, s3 = 0.f;
#pragma unroll
            for (int i = 0; i < 32; i += 4) {
                s0 += row[i + 0];
                s1 += row[i + 1];
                s2 += row[i + 2];
                s3 += row[i + 3];
            }
            float r = (s0 + s1) + (s2 + s3) + b2v;
            r = (r > 0.f) ? r : 0.01f * r;   // leaky_relu
            g_raw[cb + lane] = r;            // coalesced
        }
        __syncwarp();
    }
}

// ---------------- segment softmax + weighted aggregation ----------------
__global__ void softagg_kernel(const float* __restrict__ x) {
    int warp = (blockIdx.x * blockDim.x + threadIdx.x) >> 5;
    int lane = threadIdx.x & 31;
    if (warp >= N_NODES) return;
    int start = g_rowptr[warp];
    int deg = g_rowptr[warp + 1] - start;

    float m = -1e30f;
    for (int i = lane; i < deg; i += 32) m = fmaxf(m, g_raw[start + i]);
#pragma unroll
    for (int o = 16; o; o >>= 1) m = fmaxf(m, __shfl_xor_sync(0xffffffffu, m, o));

    float acc0 = 0.f, acc1 = 0.f, ws = 0.f;
    for (int base = 0; base < deg; base += 32) {
        int i = base + lane;
        float w = (i < deg) ? __expf(g_raw[start + i] - m) : 0.f;
        int sv = (i < deg) ? g_ss[start + i] : 0;
        ws += w;
        int cnt = min(32, deg - base);
        for (int t = 0; t < cnt; t++) {
            float wt = __shfl_sync(0xffffffffu, w, t);
            int st = __shfl_sync(0xffffffffu, sv, t);
            acc0 = fmaf(wt, x[(size_t)st * 64 + lane], acc0);
            acc1 = fmaf(wt, x[(size_t)st * 64 + 32 + lane], acc1);
        }
    }
#pragma unroll
    for (int o = 16; o; o >>= 1) ws += __shfl_xor_sync(0xffffffffu, ws, o);
    float scale = 1.f / (ws + 1e-9f);
    g_agg[warp * 64 + lane] = acc0 * scale;
    g_agg[warp * 64 + 32 + lane] = acc1 * scale;
}

// ---------------- fused 2-layer update MLP (register-tiled) ----------------
__global__ void update_kernel(const float* __restrict__ x,
                              const float* __restrict__ w1,
                              const float* __restrict__ b1,
                              const float* __restrict__ w2,
                              const float* __restrict__ b2,
                              float* __restrict__ out) {
    extern __shared__ float sm[];
    float* W1t = sm;                    // [f][j]: 128 x 128
    float* W2t = W1t + 128 * 128;       // [j][o]: 128 x 64
    float* Xs  = W2t + 128 * 64;        // [n][f]: 64 x 129
    float* Hs  = Xs + 64 * 129;         // [j][n]: 128 x 68
    float* b1s = Hs + 128 * 68;         // 128
    float* b2s = b1s + 128;             // 64
    int tid = threadIdx.x;

    for (int idx = tid; idx < 128 * 128; idx += 256) {
        int j = idx >> 7, f = idx & 127;
        W1t[f * 128 + j] = w1[idx];
    }
    for (int idx = tid; idx < 64 * 128; idx += 256) {
        int o = idx >> 7, j = idx & 127;
        W2t[j * 64 + o] = w2[idx];
    }
    if (tid < 128) b1s[tid] = b1[tid];
    if (tid < 64) b2s[tid] = b2[tid];
    __syncthreads();

    int tn = tid & 15;
    int tj = tid >> 4;
    const int NCH = (N_NODES + 63) / 64;

    for (int c = blockIdx.x; c < NCH; c += gridDim.x) {
        int n0 = c * 64;
        for (int idx = tid; idx < 64 * 128; idx += 256) {
            int n = idx >> 7, f = idx & 127;
            int nd = n0 + n;
            float v = 0.f;
            if (nd < N_NODES)
                v = (f < 64) ? x[nd * 64 + f] : g_agg[nd * 64 + (f - 64)];
            Xs[n * 129 + f] = v;
        }
        __syncthreads();

        {   // stage 1
            float acc[8][4];
#pragma unroll
            for (int jj = 0; jj < 8; jj++)
#pragma unroll
                for (int nn = 0; nn < 4; nn++) acc[jj][nn] = 0.f;

            for (int f = 0; f < 128; f++) {
                float4 w0 = *(const float4*)&W1t[f * 128 + tj * 8];
                float4 w1v = *(const float4*)&W1t[f * 128 + tj * 8 + 4];
                float wv[8] = {w0.x, w0.y, w0.z, w0.w, w1v.x, w1v.y, w1v.z, w1v.w};
                float xv[4];
#pragma unroll
                for (int nn = 0; nn < 4; nn++) xv[nn] = Xs[(tn * 4 + nn) * 129 + f];
#pragma unroll
                for (int jj = 0; jj < 8; jj++)
#pragma unroll
                    for (int nn = 0; nn < 4; nn++)
                        acc[jj][nn] = fmaf(wv[jj], xv[nn], acc[jj][nn]);
            }
#pragma unroll
            for (int jj = 0; jj < 8; jj++) {
                float b = b1s[tj * 8 + jj];
                float4 hv = {fmaxf(acc[jj][0] + b, 0.f), fmaxf(acc[jj][1] + b, 0.f),
                             fmaxf(acc[jj][2] + b, 0.f), fmaxf(acc[jj][3] + b, 0.f)};
                *(float4*)&Hs[(tj * 8 + jj) * 68 + tn * 4] = hv;
            }
        }
        __syncthreads();

        {   // stage 2
            int to = tid & 15;
            int tn2 = tid >> 4;
            float acc2[4][4];
#pragma unroll
            for (int nn = 0; nn < 4; nn++)
#pragma unroll
                for (int oo = 0; oo < 4; oo++) acc2[nn][oo] = 0.f;

            for (int j = 0; j < 128; j++) {
                float4 wv = *(const float4*)&W2t[j * 64 + to * 4];
                float4 hv = *(const float4*)&Hs[j * 68 + tn2 * 4];
                float h[4] = {hv.x, hv.y, hv.z, hv.w};
                float w[4] = {wv.x, wv.y, wv.z, wv.w};
#pragma unroll
                for (int nn = 0; nn < 4; nn++)
#pragma unroll
                    for (int oo = 0; oo < 4; oo++)
                        acc2[nn][oo] = fmaf(w[oo], h[nn], acc2[nn][oo]);
            }
#pragma unroll
            for (int nn = 0; nn < 4; nn++) {
                int nd = n0 + tn2 * 4 + nn;
                if (nd < N_NODES) {
                    float4 ov = {fmaxf(acc2[nn][0] + b2s[to * 4 + 0], 0.f),
                                 fmaxf(acc2[nn][1] + b2s[to * 4 + 1], 0.f),
                                 fmaxf(acc2[nn][2] + b2s[to * 4 + 2], 0.f),
                                 fmaxf(acc2[nn][3] + b2s[to * 4 + 3], 0.f)};
                    *(float4*)&out[nd * 64 + to * 4] = ov;
                }
            }
        }
        __syncthreads();
    }
}

// ---------------- launch ----------------
extern "C" void kernel_launch(void* const* d_in, const int* in_sizes, int n_in,
                              void* d_out, int out_size) {
    const float* x      = (const float*)d_in[0];
    const float* x_s    = (const float*)d_in[1];
    const int*   eidx   = (const int*)d_in[2];
    const float* efeat  = (const float*)d_in[3];
    const float* att_w1 = (const float*)d_in[4];
    const float* att_b1 = (const float*)d_in[5];
    const float* att_w2 = (const float*)d_in[6];
    const float* att_b2 = (const float*)d_in[7];
    const float* upd_w1 = (const float*)d_in[8];
    const float* upd_b1 = (const float*)d_in[9];
    const float* upd_w2 = (const float*)d_in[10];
    const float* upd_b2 = (const float*)d_in[11];
    float* out = (float*)d_out;

    const int PROJ_SMEM = (80 * 288 + 16 * 81) * (int)sizeof(float);
    const int UPD_SMEM  = (128 * 128 + 128 * 64 + 64 * 129 + 128 * 68 + 128 + 64) * (int)sizeof(float);
    cudaFuncSetAttribute(proj_kernel, cudaFuncAttributeMaxDynamicSharedMemorySize, PROJ_SMEM);
    cudaFuncSetAttribute(update_kernel, cudaFuncAttributeMaxDynamicSharedMemorySize, UPD_SMEM);

    // CSR build
    csr_reset_kernel<<<(N_NODES + 1023) / 1024, 1024>>>();
    csr_build_kernel<<<CSR_BLOCKS, 512>>>(eidx);

    // per-edge ef projection (dense GEMM, original edge order)
    efproj_kernel<<<2048, 288>>>(efeat, att_w1);

    // node projections (b1 folded into Pdst)
    proj_kernel<<<296, 288, PROJ_SMEM>>>(x, x_s, att_w1, att_b1);

    // edge attention scores (pure gather-reduce)
    score_kernel<<<2048, 128>>>(att_w2, att_b2);

    // segment softmax + aggregation
    softagg_kernel<<<(N_NODES * 32 + 255) / 256, 256>>>(x);

    // update MLP
    update_kernel<<<148, 256, UPD_SMEM>>>(x, upd_w1, upd_b1, upd_w2, upd_b2, out);
}

// round 11
// speedup vs baseline: 1.3329x; 1.3329x over previous
#include <cuda_runtime.h>
#include <math.h>

#define N_NODES 50000
#define N_EDGES 800000
#define H 64
#define S 16
#define EF 16
#define ATT_W 144
#define UPD_W 128
#define CSR_BLOCKS 148
#define CSR_CH 338          // ceil(50000/148)

// ---------------- scratch (static device allocations) ----------------
// +32 pad: allows unpredicated k=4 tail loads (statics are zero-initialized,
// never written -> pad stays 0; multiplied by zero weights).
__device__ float g_Psrc[N_NODES * ATT_W + 32];
__device__ float g_Pdst[N_NODES * ATT_W + 32];   // includes att_b1 folded in
__device__ float g_raw[N_EDGES];            // CSR-ordered raw scores
__device__ float g_agg[N_NODES * H];
__device__ int   g_deg[N_NODES];
__device__ int   g_rowptr[N_NODES + 1];
__device__ int   g_cursor[N_NODES];
__device__ int   g_es[N_EDGES];             // CSR-ordered original edge id
__device__ int   g_ss[N_EDGES];             // CSR-ordered src
__device__ int   g_ds[N_EDGES];             // CSR-ordered dst
__device__ int   g_bsum[CSR_BLOCKS];
__device__ unsigned int g_count;

// ---------------- f32x2 packed helpers ----------------
__device__ __forceinline__ unsigned long long pk2(float lo, float hi) {
    unsigned long long r;
    asm("mov.b64 %0, {%1, %2};" : "=l"(r) : "f"(lo), "f"(hi));
    return r;
}
__device__ __forceinline__ void upk2(unsigned long long v, float& lo, float& hi) {
    asm("mov.b64 {%0, %1}, %2;" : "=f"(lo), "=f"(hi) : "l"(v));
}
__device__ __forceinline__ unsigned long long ffma2(unsigned long long a,
                                                    unsigned long long b,
                                                    unsigned long long c) {
    unsigned long long d;
    asm("fma.rn.f32x2 %0, %1, %2, %3;" : "=l"(d) : "l"(a), "l"(b), "l"(c));
    return d;
}

// ---------------- CSR: reset then fused build ----------------
__global__ void csr_reset_kernel() {
    int i = blockIdx.x * blockDim.x + threadIdx.x;
    if (i < N_NODES) { g_deg[i] = 0; g_cursor[i] = 0; }
    if (i == 0) g_count = 0u;
}

__device__ __forceinline__ void gbar(int phase) {
    __syncthreads();
    if (threadIdx.x == 0) {
        __threadfence();
        atomicAdd(&g_count, 1u);
        while (*((volatile unsigned int*)&g_count) < (unsigned)(phase * CSR_BLOCKS)) { }
        __threadfence();
    }
    __syncthreads();
}

__global__ void __launch_bounds__(512) csr_build_kernel(const int* __restrict__ ei) {
    __shared__ int ssum[512];
    __shared__ int boff[CSR_BLOCKS];
    int t = threadIdx.x;
    int gid = blockIdx.x * 512 + t;

    // phase 1: degree histogram
    for (int e = gid; e < N_EDGES; e += CSR_BLOCKS * 512)
        atomicAdd(&g_deg[ei[N_EDGES + e]], 1);
    gbar(1);

    // phase 2: per-block inclusive scan of this block's node chunk
    int nbase = blockIdx.x * CSR_CH;
    int node = nbase + t;
    int dv = 0;
    if (t < CSR_CH && node < N_NODES) dv = g_deg[node];
    ssum[t] = dv;
    __syncthreads();
    for (int off = 1; off < 512; off <<= 1) {
        int v = (t >= off) ? ssum[t - off] : 0;
        __syncthreads();
        ssum[t] += v;
        __syncthreads();
    }
    int incl = ssum[t];
    if (t == 511) g_bsum[blockIdx.x] = ssum[511];
    gbar(2);

    // phase 3: exclusive scan of block sums, write rowptr
    if (t < CSR_BLOCKS) boff[t] = g_bsum[t];
    __syncthreads();
    if (t == 0) {
        int run = 0;
        for (int b = 0; b < CSR_BLOCKS; b++) { int tmp = boff[b]; boff[b] = run; run += tmp; }
    }
    __syncthreads();
    int myoff = boff[blockIdx.x];
    if (t < CSR_CH && node < N_NODES) g_rowptr[node] = myoff + incl - dv;
    if (blockIdx.x == 0 && t == 0) g_rowptr[N_NODES] = N_EDGES;
    gbar(3);

    // phase 4: fill (CSR-ordered edge id + src + dst)
    for (int e = gid; e < N_EDGES; e += CSR_BLOCKS * 512) {
        int s = ei[e];
        int d = ei[N_EDGES + e];
        int pos = g_rowptr[d] + atomicAdd(&g_cursor[d], 1);
        g_es[pos] = e;
        g_ss[pos] = s;
        g_ds[pos] = d;
    }
}

// ---------------- node projections (register-tiled GEMM) ----------------
// b1 is folded into the Pdst half.
__global__ void proj_kernel(const float* __restrict__ x,
                            const float* __restrict__ xs,
                            const float* __restrict__ w1,
                            const float* __restrict__ b1) {
    extern __shared__ float sm[];
    float* Wt = sm;                 // [f][j]: 80 x 288
    float* Xs = Wt + 80 * 288;      // [n][f]: 16 x 81 (pad)
    __shared__ float b1s[144];
    int tid = threadIdx.x;

    for (int idx = tid; idx < 80 * 288; idx += blockDim.x) {
        int j = idx % 288, f = idx / 288;
        int jr = (j < 144) ? j : j - 144;
        int col;
        if (j < 144) col = (f < 64) ? f : 64 + f;        // x[src] | xs[src]
        else         col = (f < 64) ? 64 + f : 80 + f;   // x[dst] | xs[dst]
        Wt[f * 288 + j] = w1[jr * 176 + col];
    }
    if (tid < 144) b1s[tid] = b1[tid];
    __syncthreads();

    int tj = tid >> 3;      // 0..35
    int tn = tid & 7;       // 0..7
    const int NCH = N_NODES / 16;   // 3125 exact

    for (int c = blockIdx.x; c < NCH; c += gridDim.x) {
        int n0 = c * 16;
        for (int idx = tid; idx < 16 * 80; idx += blockDim.x) {
            int n = idx / 80, f = idx % 80;
            int nd = n0 + n;
            Xs[n * 81 + f] = (f < 64) ? x[nd * 64 + f] : xs[nd * 16 + (f - 64)];
        }
        __syncthreads();

        float acc[8][2];
#pragma unroll
        for (int jj = 0; jj < 8; jj++) { acc[jj][0] = 0.f; acc[jj][1] = 0.f; }

        for (int f = 0; f < 80; f++) {
            float4 w0 = *(const float4*)&Wt[f * 288 + tj * 8];
            float4 w1v = *(const float4*)&Wt[f * 288 + tj * 8 + 4];
            float x0 = Xs[(tn * 2 + 0) * 81 + f];
            float x1 = Xs[(tn * 2 + 1) * 81 + f];
            float wv[8] = {w0.x, w0.y, w0.z, w0.w, w1v.x, w1v.y, w1v.z, w1v.w};
#pragma unroll
            for (int jj = 0; jj < 8; jj++) {
                acc[jj][0] = fmaf(wv[jj], x0, acc[jj][0]);
                acc[jj][1] = fmaf(wv[jj], x1, acc[jj][1]);
            }
        }

#pragma unroll
        for (int u = 0; u < 2; u++) {
            int nd = n0 + tn * 2 + u;
            int j = tj * 8;
            if (j < 144) {
                float4 o0 = {acc[0][u], acc[1][u], acc[2][u], acc[3][u]};
                float4 o1 = {acc[4][u], acc[5][u], acc[6][u], acc[7][u]};
                *(float4*)&g_Psrc[nd * 144 + j] = o0;
                *(float4*)&g_Psrc[nd * 144 + j + 4] = o1;
            } else {
                int jb = j - 144;
                float4 o0 = {acc[0][u] + b1s[jb + 0], acc[1][u] + b1s[jb + 1],
                             acc[2][u] + b1s[jb + 2], acc[3][u] + b1s[jb + 3]};
                float4 o1 = {acc[4][u] + b1s[jb + 4], acc[5][u] + b1s[jb + 5],
                             acc[6][u] + b1s[jb + 6], acc[7][u] + b1s[jb + 7]};
                *(float4*)&g_Pdst[nd * 144 + jb] = o0;
                *(float4*)&g_Pdst[nd * 144 + jb + 4] = o1;
            }
        }
        __syncthreads();
    }
}

// ---------------- edge score kernel: warp/edge k-major, high occupancy ----------
// Lane handles j = lane + 32k (k=0..4). Per edge: 10 unpredicated single-line
// LDGs (padded arrays), acc seeded pk2(ps,pd) (lo+hi absorbs the add),
// fp-outer loop keeps ONE ef pair live. Transpose-sum per 32 edges.
__global__ void __launch_bounds__(128, 4) score_kernel(
        const float* __restrict__ ef,
        const float* __restrict__ w1,
        const float* __restrict__ w2, const float* __restrict__ b2) {
    __shared__ float part[4][32 * 33];
    int tid = threadIdx.x;
    int lane = tid & 31;
    int wip = tid >> 5;
    float* myPart = part[wip];

    // packed ef-projection weights in registers: wP[fp][k], j = lane+32k
    unsigned long long wP[8][5];
    float w2r[5];
#pragma unroll
    for (int k = 0; k < 5; k++) {
        int j = lane + 32 * k;
        bool v = (j < 144);
        w2r[k] = v ? w2[j] : 0.f;
#pragma unroll
        for (int fp = 0; fp < 8; fp++) {
            float wlo = v ? w1[j * 176 + 160 + 2 * fp] : 0.f;
            float whi = v ? w1[j * 176 + 160 + 2 * fp + 1] : 0.f;
            wP[fp][k] = pk2(wlo, whi);
        }
    }
    float b2v = b2[0];

    int gw = (blockIdx.x * blockDim.x + tid) >> 5;
    int nw = (gridDim.x * blockDim.x) >> 5;
    int chunk = (N_EDGES + nw - 1) / nw;
    int p0 = gw * chunk;
    int p1 = min(p0 + chunk, N_EDGES);

    for (int cb = p0; cb < p1; cb += 32) {
        int cd = min(32, p1 - cb);      // warp-uniform

        int myS = (lane < cd) ? g_ss[cb + lane] : 0;
        int myD = (lane < cd) ? g_ds[cb + lane] : 0;
        int myE = (lane < cd) ? g_es[cb + lane] : 0;

        for (int t = 0; t < cd; t++) {
            int s = __shfl_sync(0xffffffffu, myS, t);
            int d = __shfl_sync(0xffffffffu, myD, t);
            int e = __shfl_sync(0xffffffffu, myE, t);

            const float* psrow = &g_Psrc[(size_t)s * 144];
            const float* pdrow = &g_Pdst[(size_t)d * 144];

            // acc[k] = (ps, pd) packed: lo accumulates even-f + ps,
            // hi odd-f + pd; final lo+hi = ps+pd+c. Unpredicated loads
            // (arrays padded; zero weights nullify lanes>=16 at k=4).
            unsigned long long acc[5];
#pragma unroll
            for (int k = 0; k < 5; k++)
                acc[k] = pk2(psrow[lane + 32 * k], pdrow[lane + 32 * k]);

            const float2* efp2 = (const float2*)(ef + (size_t)e * 16);
#pragma unroll
            for (int fp = 0; fp < 8; fp++) {
                float2 ev = efp2[fp];               // uniform broadcast load
                unsigned long long v = pk2(ev.x, ev.y);
#pragma unroll
                for (int k = 0; k < 5; k++)
                    acc[k] = ffma2(v, wP[fp][k], acc[k]);
            }

            float p = 0.f;
#pragma unroll
            for (int k = 0; k < 5; k++) {
                float lo, hi; upk2(acc[k], lo, hi);
                p = fmaf(fmaxf(lo + hi, 0.f), w2r[k], p);
            }
            myPart[t * 33 + lane] = p;   // STS ends the chain
        }
        __syncwarp();

        // transpose-sum: lane t sums row t (conflict-free: bank=(t+i)&31)
        if (lane < cd) {
            const float* row = &myPart[lane * 33];
            float s0 = 0.f, s1 = 0.f, s2 = 0.f, s3 = 0.f;
#pragma unroll
            for (int i = 0; i < 32; i += 4) {
                s0 += row[i + 0];
                s1 += row[i + 1];
                s2 += row[i + 2];
                s3 += row[i + 3];
            }
            float r = (s0 + s1) + (s2 + s3) + b2v;
            r = (r > 0.f) ? r : 0.01f * r;   // leaky_relu
            g_raw[cb + lane] = r;            // coalesced
        }
        __syncwarp();
    }
}

// ---------------- segment softmax + weighted aggregation ----------------
__global__ void softagg_kernel(const float* __restrict__ x) {
    int warp = (blockIdx.x * blockDim.x + threadIdx.x) >> 5;
    int lane = threadIdx.x & 31;
    if (warp >= N_NODES) return;
    int start = g_rowptr[warp];
    int deg = g_rowptr[warp + 1] - start;

    float m = -1e30f;
    for (int i = lane; i < deg; i += 32) m = fmaxf(m, g_raw[start + i]);
#pragma unroll
    for (int o = 16; o; o >>= 1) m = fmaxf(m, __shfl_xor_sync(0xffffffffu, m, o));

    float acc0 = 0.f, acc1 = 0.f, ws = 0.f;
    for (int base = 0; base < deg; base += 32) {
        int i = base + lane;
        float w = (i < deg) ? __expf(g_raw[start + i] - m) : 0.f;
        int sv = (i < deg) ? g_ss[start + i] : 0;
        ws += w;
        int cnt = min(32, deg - base);
        for (int t = 0; t < cnt; t++) {
            float wt = __shfl_sync(0xffffffffu, w, t);
            int st = __shfl_sync(0xffffffffu, sv, t);
            acc0 = fmaf(wt, x[(size_t)st * 64 + lane], acc0);
            acc1 = fmaf(wt, x[(size_t)st * 64 + 32 + lane], acc1);
        }
    }
#pragma unroll
    for (int o = 16; o; o >>= 1) ws += __shfl_xor_sync(0xffffffffu, ws, o);
    float scale = 1.f / (ws + 1e-9f);
    g_agg[warp * 64 + lane] = acc0 * scale;
    g_agg[warp * 64 + 32 + lane] = acc1 * scale;
}

// ---------------- fused 2-layer update MLP (register-tiled) ----------------
__global__ void update_kernel(const float* __restrict__ x,
                              const float* __restrict__ w1,
                              const float* __restrict__ b1,
                              const float* __restrict__ w2,
                              const float* __restrict__ b2,
                              float* __restrict__ out) {
    extern __shared__ float sm[];
    float* W1t = sm;                    // [f][j]: 128 x 128
    float* W2t = W1t + 128 * 128;       // [j][o]: 128 x 64
    float* Xs  = W2t + 128 * 64;        // [n][f]: 64 x 129
    float* Hs  = Xs + 64 * 129;         // [j][n]: 128 x 68
    float* b1s = Hs + 128 * 68;         // 128
    float* b2s = b1s + 128;             // 64
    int tid = threadIdx.x;

    for (int idx = tid; idx < 128 * 128; idx += 256) {
        int j = idx >> 7, f = idx & 127;
        W1t[f * 128 + j] = w1[idx];
    }
    for (int idx = tid; idx < 64 * 128; idx += 256) {
        int o = idx >> 7, j = idx & 127;
        W2t[j * 64 + o] = w2[idx];
    }
    if (tid < 128) b1s[tid] = b1[tid];
    if (tid < 64) b2s[tid] = b2[tid];
    __syncthreads();

    int tn = tid & 15;
    int tj = tid >> 4;
    const int NCH = (N_NODES + 63) / 64;

    for (int c = blockIdx.x; c < NCH; c += gridDim.x) {
        int n0 = c * 64;
        for (int idx = tid; idx < 64 * 128; idx += 256) {
            int n = idx >> 7, f = idx & 127;
            int nd = n0 + n;
            float v = 0.f;
            if (nd < N_NODES)
                v = (f < 64) ? x[nd * 64 + f] : g_agg[nd * 64 + (f - 64)];
            Xs[n * 129 + f] = v;
        }
        __syncthreads();

        {   // stage 1
            float acc[8][4];
#pragma unroll
            for (int jj = 0; jj < 8; jj++)
#pragma unroll
                for (int nn = 0; nn < 4; nn++) acc[jj][nn] = 0.f;

            for (int f = 0; f < 128; f++) {
                float4 w0 = *(const float4*)&W1t[f * 128 + tj * 8];
                float4 w1v = *(const float4*)&W1t[f * 128 + tj * 8 + 4];
                float wv[8] = {w0.x, w0.y, w0.z, w0.w, w1v.x, w1v.y, w1v.z, w1v.w};
                float xv[4];
#pragma unroll
                for (int nn = 0; nn < 4; nn++) xv[nn] = Xs[(tn * 4 + nn) * 129 + f];
#pragma unroll
                for (int jj = 0; jj < 8; jj++)
#pragma unroll
                    for (int nn = 0; nn < 4; nn++)
                        acc[jj][nn] = fmaf(wv[jj], xv[nn], acc[jj][nn]);
            }
#pragma unroll
            for (int jj = 0; jj < 8; jj++) {
                float b = b1s[tj * 8 + jj];
                float4 hv = {fmaxf(acc[jj][0] + b, 0.f), fmaxf(acc[jj][1] + b, 0.f),
                             fmaxf(acc[jj][2] + b, 0.f), fmaxf(acc[jj][3] + b, 0.f)};
                *(float4*)&Hs[(tj * 8 + jj) * 68 + tn * 4] = hv;
            }
        }
        __syncthreads();

        {   // stage 2
            int to = tid & 15;
            int tn2 = tid >> 4;
            float acc2[4][4];
#pragma unroll
            for (int nn = 0; nn < 4; nn++)
#pragma unroll
                for (int oo = 0; oo < 4; oo++) acc2[nn][oo] = 0.f;

            for (int j = 0; j < 128; j++) {
                float4 wv = *(const float4*)&W2t[j * 64 + to * 4];
                float4 hv = *(const float4*)&Hs[j * 68 + tn2 * 4];
                float h[4] = {hv.x, hv.y, hv.z, hv.w};
                float w[4] = {wv.x, wv.y, wv.z, wv.w};
#pragma unroll
                for (int nn = 0; nn < 4; nn++)
#pragma unroll
                    for (int oo = 0; oo < 4; oo++)
                        acc2[nn][oo] = fmaf(w[oo], h[nn], acc2[nn][oo]);
            }
#pragma unroll
            for (int nn = 0; nn < 4; nn++) {
                int nd = n0 + tn2 * 4 + nn;
                if (nd < N_NODES) {
                    float4 ov = {fmaxf(acc2[nn][0] + b2s[to * 4 + 0], 0.f),
                                 fmaxf(acc2[nn][1] + b2s[to * 4 + 1], 0.f),
                                 fmaxf(acc2[nn][2] + b2s[to * 4 + 2], 0.f),
                                 fmaxf(acc2[nn][3] + b2s[to * 4 + 3], 0.f)};
                    *(float4*)&out[nd * 64 + to * 4] = ov;
                }
            }
        }
        __syncthreads();
    }
}

// ---------------- launch ----------------
extern "C" void kernel_launch(void* const* d_in, const int* in_sizes, int n_in,
                              void* d_out, int out_size) {
    const float* x      = (const float*)d_in[0];
    const float* x_s    = (const float*)d_in[1];
    const int*   eidx   = (const int*)d_in[2];
    const float* efeat  = (const float*)d_in[3];
    const float* att_w1 = (const float*)d_in[4];
    const float* att_b1 = (const float*)d_in[5];
    const float* att_w2 = (const float*)d_in[6];
    const float* att_b2 = (const float*)d_in[7];
    const float* upd_w1 = (const float*)d_in[8];
    const float* upd_b1 = (const float*)d_in[9];
    const float* upd_w2 = (const float*)d_in[10];
    const float* upd_b2 = (const float*)d_in[11];
    float* out = (float*)d_out;

    const int PROJ_SMEM = (80 * 288 + 16 * 81) * (int)sizeof(float);
    const int UPD_SMEM  = (128 * 128 + 128 * 64 + 64 * 129 + 128 * 68 + 128 + 64) * (int)sizeof(float);
    cudaFuncSetAttribute(proj_kernel, cudaFuncAttributeMaxDynamicSharedMemorySize, PROJ_SMEM);
    cudaFuncSetAttribute(update_kernel, cudaFuncAttributeMaxDynamicSharedMemorySize, UPD_SMEM);

    // CSR build
    csr_reset_kernel<<<(N_NODES + 1023) / 1024, 1024>>>();
    csr_build_kernel<<<CSR_BLOCKS, 512>>>(eidx);

    // node projections (b1 folded into Pdst)
    proj_kernel<<<296, 288, PROJ_SMEM>>>(x, x_s, att_w1, att_b1);

    // edge attention scores (warp/edge k-major, 4 blocks/SM)
    score_kernel<<<2048, 128>>>(efeat, att_w1, att_w2, att_b2);

    // segment softmax + aggregation
    softagg_kernel<<<(N_NODES * 32 + 255) / 256, 256>>>(x);

    // update MLP
    update_kernel<<<148, 256, UPD_SMEM>>>(x, upd_w1, upd_b1, upd_w2, upd_b2, out);
}

// round 12
// speedup vs baseline: 1.4028x; 1.0524x over previous
#include <cuda_runtime.h>
#include <math.h>

#define N_NODES 50000
#define N_EDGES 800000
#define H 64
#define S 16
#define EF 16
#define ATT_W 144
#define UPD_W 128
#define CSR_BLOCKS 148
#define CSR_CH 338          // ceil(50000/148)

// ---------------- scratch (static device allocations) ----------------
// +32 pad: allows unpredicated tail loads (statics zero-initialized; pad
// never written; tail contributions multiplied by zero weights).
__device__ float g_Psrc[N_NODES * ATT_W + 32];
__device__ float g_Pdst[N_NODES * ATT_W + 32];   // includes att_b1 folded in
__device__ float g_raw[N_EDGES];            // CSR-ordered raw scores
__device__ float g_agg[N_NODES * H];
__device__ int   g_deg[N_NODES];
__device__ int   g_rowptr[N_NODES + 1];
__device__ int   g_cursor[N_NODES];
__device__ int   g_es[N_EDGES];             // CSR-ordered original edge id
__device__ int   g_ss[N_EDGES];             // CSR-ordered src
__device__ int   g_ds[N_EDGES];             // CSR-ordered dst
__device__ int   g_bsum[CSR_BLOCKS];
__device__ unsigned int g_count;

// ---------------- f32x2 packed helpers ----------------
__device__ __forceinline__ unsigned long long pk2(float lo, float hi) {
    unsigned long long r;
    asm("mov.b64 %0, {%1, %2};" : "=l"(r) : "f"(lo), "f"(hi));
    return r;
}
__device__ __forceinline__ void upk2(unsigned long long v, float& lo, float& hi) {
    asm("mov.b64 {%0, %1}, %2;" : "=f"(lo), "=f"(hi) : "l"(v));
}
__device__ __forceinline__ unsigned long long ffma2(unsigned long long a,
                                                    unsigned long long b,
                                                    unsigned long long c) {
    unsigned long long d;
    asm("fma.rn.f32x2 %0, %1, %2, %3;" : "=l"(d) : "l"(a), "l"(b), "l"(c));
    return d;
}

// ---------------- CSR: reset then fused build ----------------
__global__ void csr_reset_kernel() {
    int i = blockIdx.x * blockDim.x + threadIdx.x;
    if (i < N_NODES) { g_deg[i] = 0; g_cursor[i] = 0; }
    if (i == 0) g_count = 0u;
}

__device__ __forceinline__ void gbar(int phase) {
    __syncthreads();
    if (threadIdx.x == 0) {
        __threadfence();
        atomicAdd(&g_count, 1u);
        while (*((volatile unsigned int*)&g_count) < (unsigned)(phase * CSR_BLOCKS)) { }
        __threadfence();
    }
    __syncthreads();
}

__global__ void __launch_bounds__(512) csr_build_kernel(const int* __restrict__ ei) {
    __shared__ int ssum[512];
    __shared__ int boff[CSR_BLOCKS];
    int t = threadIdx.x;
    int gid = blockIdx.x * 512 + t;

    // phase 1: degree histogram
    for (int e = gid; e < N_EDGES; e += CSR_BLOCKS * 512)
        atomicAdd(&g_deg[ei[N_EDGES + e]], 1);
    gbar(1);

    // phase 2: per-block inclusive scan of this block's node chunk
    int nbase = blockIdx.x * CSR_CH;
    int node = nbase + t;
    int dv = 0;
    if (t < CSR_CH && node < N_NODES) dv = g_deg[node];
    ssum[t] = dv;
    __syncthreads();
    for (int off = 1; off < 512; off <<= 1) {
        int v = (t >= off) ? ssum[t - off] : 0;
        __syncthreads();
        ssum[t] += v;
        __syncthreads();
    }
    int incl = ssum[t];
    if (t == 511) g_bsum[blockIdx.x] = ssum[511];
    gbar(2);

    // phase 3: exclusive scan of block sums, write rowptr
    if (t < CSR_BLOCKS) boff[t] = g_bsum[t];
    __syncthreads();
    if (t == 0) {
        int run = 0;
        for (int b = 0; b < CSR_BLOCKS; b++) { int tmp = boff[b]; boff[b] = run; run += tmp; }
    }
    __syncthreads();
    int myoff = boff[blockIdx.x];
    if (t < CSR_CH && node < N_NODES) g_rowptr[node] = myoff + incl - dv;
    if (blockIdx.x == 0 && t == 0) g_rowptr[N_NODES] = N_EDGES;
    gbar(3);

    // phase 4: fill (CSR-ordered edge id + src + dst)
    for (int e = gid; e < N_EDGES; e += CSR_BLOCKS * 512) {
        int s = ei[e];
        int d = ei[N_EDGES + e];
        int pos = g_rowptr[d] + atomicAdd(&g_cursor[d], 1);
        g_es[pos] = e;
        g_ss[pos] = s;
        g_ds[pos] = d;
    }
}

// ---------------- node projections (register-tiled GEMM) ----------------
// b1 is folded into the Pdst half.
__global__ void proj_kernel(const float* __restrict__ x,
                            const float* __restrict__ xs,
                            const float* __restrict__ w1,
                            const float* __restrict__ b1) {
    extern __shared__ float sm[];
    float* Wt = sm;                 // [f][j]: 80 x 288
    float* Xs = Wt + 80 * 288;      // [n][f]: 16 x 81 (pad)
    __shared__ float b1s[144];
    int tid = threadIdx.x;

    for (int idx = tid; idx < 80 * 288; idx += blockDim.x) {
        int j = idx % 288, f = idx / 288;
        int jr = (j < 144) ? j : j - 144;
        int col;
        if (j < 144) col = (f < 64) ? f : 64 + f;        // x[src] | xs[src]
        else         col = (f < 64) ? 64 + f : 80 + f;   // x[dst] | xs[dst]
        Wt[f * 288 + j] = w1[jr * 176 + col];
    }
    if (tid < 144) b1s[tid] = b1[tid];
    __syncthreads();

    int tj = tid >> 3;      // 0..35
    int tn = tid & 7;       // 0..7
    const int NCH = N_NODES / 16;   // 3125 exact

    for (int c = blockIdx.x; c < NCH; c += gridDim.x) {
        int n0 = c * 16;
        for (int idx = tid; idx < 16 * 80; idx += blockDim.x) {
            int n = idx / 80, f = idx % 80;
            int nd = n0 + n;
            Xs[n * 81 + f] = (f < 64) ? x[nd * 64 + f] : xs[nd * 16 + (f - 64)];
        }
        __syncthreads();

        float acc[8][2];
#pragma unroll
        for (int jj = 0; jj < 8; jj++) { acc[jj][0] = 0.f; acc[jj][1] = 0.f; }

        for (int f = 0; f < 80; f++) {
            float4 w0 = *(const float4*)&Wt[f * 288 + tj * 8];
            float4 w1v = *(const float4*)&Wt[f * 288 + tj * 8 + 4];
            float x0 = Xs[(tn * 2 + 0) * 81 + f];
            float x1 = Xs[(tn * 2 + 1) * 81 + f];
            float wv[8] = {w0.x, w0.y, w0.z, w0.w, w1v.x, w1v.y, w1v.z, w1v.w};
#pragma unroll
            for (int jj = 0; jj < 8; jj++) {
                acc[jj][0] = fmaf(wv[jj], x0, acc[jj][0]);
                acc[jj][1] = fmaf(wv[jj], x1, acc[jj][1]);
            }
        }

#pragma unroll
        for (int u = 0; u < 2; u++) {
            int nd = n0 + tn * 2 + u;
            int j = tj * 8;
            if (j < 144) {
                float4 o0 = {acc[0][u], acc[1][u], acc[2][u], acc[3][u]};
                float4 o1 = {acc[4][u], acc[5][u], acc[6][u], acc[7][u]};
                *(float4*)&g_Psrc[nd * 144 + j] = o0;
                *(float4*)&g_Psrc[nd * 144 + j + 4] = o1;
            } else {
                int jb = j - 144;
                float4 o0 = {acc[0][u] + b1s[jb + 0], acc[1][u] + b1s[jb + 1],
                             acc[2][u] + b1s[jb + 2], acc[3][u] + b1s[jb + 3]};
                float4 o1 = {acc[4][u] + b1s[jb + 4], acc[5][u] + b1s[jb + 5],
                             acc[6][u] + b1s[jb + 6], acc[7][u] + b1s[jb + 7]};
                *(float4*)&g_Pdst[nd * 144 + jb] = o0;
                *(float4*)&g_Pdst[nd * 144 + jb + 4] = o1;
            }
        }
        __syncthreads();
    }
}

// ---------------- edge score kernel: float4 gathers, uniform meta -------------
// Lane owns j = 4*lane..4*lane+3 plus tail j = 128+lane (lane<16).
// Per edge: 3 uniform meta loads (L1-hit) + 2 LDG.128 + 2 LDG.32 gathers +
// 4 uniform LDG.128 (ef). Transpose-sum per 32 edges.
__global__ void __launch_bounds__(128, 4) score_kernel(
        const float* __restrict__ ef,
        const float* __restrict__ w1,
        const float* __restrict__ w2, const float* __restrict__ b2) {
    __shared__ float part[4][32 * 33];
    int tid = threadIdx.x;
    int lane = tid & 31;
    int wip = tid >> 5;
    float* myPart = part[wip];

    // weights: main j = 4*lane+jj, tail j = 128+lane (zeroed for lane>=16)
    unsigned long long wP[8][4];
    unsigned long long wT[8];
    float w2r[4], w2t;
#pragma unroll
    for (int jj = 0; jj < 4; jj++) {
        int j = 4 * lane + jj;              // 0..127, always valid
        w2r[jj] = w2[j];
#pragma unroll
        for (int fp = 0; fp < 8; fp++)
            wP[fp][jj] = pk2(w1[j * 176 + 160 + 2 * fp], w1[j * 176 + 160 + 2 * fp + 1]);
    }
    {
        int j = 128 + lane;
        bool v = (lane < 16);               // j<144
        w2t = v ? w2[j] : 0.f;
#pragma unroll
        for (int fp = 0; fp < 8; fp++) {
            float wlo = v ? w1[j * 176 + 160 + 2 * fp] : 0.f;
            float whi = v ? w1[j * 176 + 160 + 2 * fp + 1] : 0.f;
            wT[fp] = pk2(wlo, whi);
        }
    }
    float b2v = b2[0];

    int gw = (blockIdx.x * blockDim.x + tid) >> 5;
    int nw = (gridDim.x * blockDim.x) >> 5;
    int chunk = (N_EDGES + nw - 1) / nw;
    int p0 = gw * chunk;
    int p1 = min(p0 + chunk, N_EDGES);

    for (int cb = p0; cb < p1; cb += 32) {
        int cd = min(32, p1 - cb);      // warp-uniform

        for (int t = 0; t < cd; t++) {
            int p = cb + t;
            int s = g_ss[p];            // uniform broadcast, L1-hit
            int d = g_ds[p];
            int e = g_es[p];

            const float* psrow = &g_Psrc[(size_t)s * 144];
            const float* pdrow = &g_Pdst[(size_t)d * 144];
            float4 ps4 = *(const float4*)&psrow[4 * lane];      // LDG.128, 512B warp
            float4 pd4 = *(const float4*)&pdrow[4 * lane];
            float pst = psrow[128 + lane];      // unpredicated (padded + zero wts)
            float pdt = pdrow[128 + lane];

            const float4* ef4 = (const float4*)(ef + (size_t)e * 16);
            float4 e0 = ef4[0], e1 = ef4[1], e2 = ef4[2], e3 = ef4[3];
            unsigned long long efp[8];
            efp[0] = pk2(e0.x, e0.y); efp[1] = pk2(e0.z, e0.w);
            efp[2] = pk2(e1.x, e1.y); efp[3] = pk2(e1.z, e1.w);
            efp[4] = pk2(e2.x, e2.y); efp[5] = pk2(e2.z, e2.w);
            efp[6] = pk2(e3.x, e3.y); efp[7] = pk2(e3.z, e3.w);

            // acc = (ps, pd) packed; lo+hi at the end gives ps+pd+c (b1 in Pdst)
            unsigned long long a0 = pk2(ps4.x, pd4.x);
            unsigned long long a1 = pk2(ps4.y, pd4.y);
            unsigned long long a2 = pk2(ps4.z, pd4.z);
            unsigned long long a3 = pk2(ps4.w, pd4.w);
            unsigned long long aT = pk2(pst, pdt);
#pragma unroll
            for (int fp = 0; fp < 8; fp++) {
                unsigned long long v = efp[fp];
                a0 = ffma2(v, wP[fp][0], a0);
                a1 = ffma2(v, wP[fp][1], a1);
                a2 = ffma2(v, wP[fp][2], a2);
                a3 = ffma2(v, wP[fp][3], a3);
                aT = ffma2(v, wT[fp], aT);
            }
            float lo, hi, pr;
            upk2(a0, lo, hi); pr  = fmaxf(lo + hi, 0.f) * w2r[0];
            upk2(a1, lo, hi); pr  = fmaf(fmaxf(lo + hi, 0.f), w2r[1], pr);
            upk2(a2, lo, hi); pr  = fmaf(fmaxf(lo + hi, 0.f), w2r[2], pr);
            upk2(a3, lo, hi); pr  = fmaf(fmaxf(lo + hi, 0.f), w2r[3], pr);
            upk2(aT, lo, hi); pr  = fmaf(fmaxf(lo + hi, 0.f), w2t,   pr);

            myPart[t * 33 + lane] = pr;   // STS ends the chain
        }
        __syncwarp();

        // transpose-sum: lane t sums row t (conflict-free: bank=(t+i)&31)
        if (lane < cd) {
            const float* row = &myPart[lane * 33];
            float s0 = 0.f, s1 = 0.f, s2 = 0.f, s3 = 0.f;
#pragma unroll
            for (int i = 0; i < 32; i += 4) {
                s0 += row[i + 0];
                s1 += row[i + 1];
                s2 += row[i + 2];
                s3 += row[i + 3];
            }
            float r = (s0 + s1) + (s2 + s3) + b2v;
            r = (r > 0.f) ? r : 0.01f * r;   // leaky_relu
            g_raw[cb + lane] = r;            // coalesced
        }
        __syncwarp();
    }
}

// ---------------- segment softmax + weighted aggregation ----------------
__global__ void softagg_kernel(const float* __restrict__ x) {
    int warp = (blockIdx.x * blockDim.x + threadIdx.x) >> 5;
    int lane = threadIdx.x & 31;
    if (warp >= N_NODES) return;
    int start = g_rowptr[warp];
    int deg = g_rowptr[warp + 1] - start;

    float m = -1e30f;
    for (int i = lane; i < deg; i += 32) m = fmaxf(m, g_raw[start + i]);
#pragma unroll
    for (int o = 16; o; o >>= 1) m = fmaxf(m, __shfl_xor_sync(0xffffffffu, m, o));

    float acc0 = 0.f, acc1 = 0.f, ws = 0.f;
    for (int base = 0; base < deg; base += 32) {
        int i = base + lane;
        float w = (i < deg) ? __expf(g_raw[start + i] - m) : 0.f;
        int sv = (i < deg) ? g_ss[start + i] : 0;
        ws += w;
        int cnt = min(32, deg - base);
        for (int t = 0; t < cnt; t++) {
            float wt = __shfl_sync(0xffffffffu, w, t);
            int st = __shfl_sync(0xffffffffu, sv, t);
            acc0 = fmaf(wt, x[(size_t)st * 64 + lane], acc0);
            acc1 = fmaf(wt, x[(size_t)st * 64 + 32 + lane], acc1);
        }
    }
#pragma unroll
    for (int o = 16; o; o >>= 1) ws += __shfl_xor_sync(0xffffffffu, ws, o);
    float scale = 1.f / (ws + 1e-9f);
    g_agg[warp * 64 + lane] = acc0 * scale;
    g_agg[warp * 64 + 32 + lane] = acc1 * scale;
}

// ---------------- fused 2-layer update MLP (register-tiled) ----------------
__global__ void update_kernel(const float* __restrict__ x,
                              const float* __restrict__ w1,
                              const float* __restrict__ b1,
                              const float* __restrict__ w2,
                              const float* __restrict__ b2,
                              float* __restrict__ out) {
    extern __shared__ float sm[];
    float* W1t = sm;                    // [f][j]: 128 x 128
    float* W2t = W1t + 128 * 128;       // [j][o]: 128 x 64
    float* Xs  = W2t + 128 * 64;        // [n][f]: 64 x 129
    float* Hs  = Xs + 64 * 129;         // [j][n]: 128 x 68
    float* b1s = Hs + 128 * 68;         // 128
    float* b2s = b1s + 128;             // 64
    int tid = threadIdx.x;

    for (int idx = tid; idx < 128 * 128; idx += 256) {
        int j = idx >> 7, f = idx & 127;
        W1t[f * 128 + j] = w1[idx];
    }
    for (int idx = tid; idx < 64 * 128; idx += 256) {
        int o = idx >> 7, j = idx & 127;
        W2t[j * 64 + o] = w2[idx];
    }
    if (tid < 128) b1s[tid] = b1[tid];
    if (tid < 64) b2s[tid] = b2[tid];
    __syncthreads();

    int tn = tid & 15;
    int tj = tid >> 4;
    const int NCH = (N_NODES + 63) / 64;

    for (int c = blockIdx.x; c < NCH; c += gridDim.x) {
        int n0 = c * 64;
        for (int idx = tid; idx < 64 * 128; idx += 256) {
            int n = idx >> 7, f = idx & 127;
            int nd = n0 + n;
            float v = 0.f;
            if (nd < N_NODES)
                v = (f < 64) ? x[nd * 64 + f] : g_agg[nd * 64 + (f - 64)];
            Xs[n * 129 + f] = v;
        }
        __syncthreads();

        {   // stage 1
            float acc[8][4];
#pragma unroll
            for (int jj = 0; jj < 8; jj++)
#pragma unroll
                for (int nn = 0; nn < 4; nn++) acc[jj][nn] = 0.f;

            for (int f = 0; f < 128; f++) {
                float4 w0 = *(const float4*)&W1t[f * 128 + tj * 8];
                float4 w1v = *(const float4*)&W1t[f * 128 + tj * 8 + 4];
                float wv[8] = {w0.x, w0.y, w0.z, w0.w, w1v.x, w1v.y, w1v.z, w1v.w};
                float xv[4];
#pragma unroll
                for (int nn = 0; nn < 4; nn++) xv[nn] = Xs[(tn * 4 + nn) * 129 + f];
#pragma unroll
                for (int jj = 0; jj < 8; jj++)
#pragma unroll
                    for (int nn = 0; nn < 4; nn++)
                        acc[jj][nn] = fmaf(wv[jj], xv[nn], acc[jj][nn]);
            }
#pragma unroll
            for (int jj = 0; jj < 8; jj++) {
                float b = b1s[tj * 8 + jj];
                float4 hv = {fmaxf(acc[jj][0] + b, 0.f), fmaxf(acc[jj][1] + b, 0.f),
                             fmaxf(acc[jj][2] + b, 0.f), fmaxf(acc[jj][3] + b, 0.f)};
                *(float4*)&Hs[(tj * 8 + jj) * 68 + tn * 4] = hv;
            }
        }
        __syncthreads();

        {   // stage 2
            int to = tid & 15;
            int tn2 = tid >> 4;
            float acc2[4][4];
#pragma unroll
            for (int nn = 0; nn < 4; nn++)
#pragma unroll
                for (int oo = 0; oo < 4; oo++) acc2[nn][oo] = 0.f;

            for (int j = 0; j < 128; j++) {
                float4 wv = *(const float4*)&W2t[j * 64 + to * 4];
                float4 hv = *(const float4*)&Hs[j * 68 + tn2 * 4];
                float h[4] = {hv.x, hv.y, hv.z, hv.w};
                float w[4] = {wv.x, wv.y, wv.z, wv.w};
#pragma unroll
                for (int nn = 0; nn < 4; nn++)
#pragma unroll
                    for (int oo = 0; oo < 4; oo++)
                        acc2[nn][oo] = fmaf(w[oo], h[nn], acc2[nn][oo]);
            }
#pragma unroll
            for (int nn = 0; nn < 4; nn++) {
                int nd = n0 + tn2 * 4 + nn;
                if (nd < N_NODES) {
                    float4 ov = {fmaxf(acc2[nn][0] + b2s[to * 4 + 0], 0.f),
                                 fmaxf(acc2[nn][1] + b2s[to * 4 + 1], 0.f),
                                 fmaxf(acc2[nn][2] + b2s[to * 4 + 2], 0.f),
                                 fmaxf(acc2[nn][3] + b2s[to * 4 + 3], 0.f)};
                    *(float4*)&out[nd * 64 + to * 4] = ov;
                }
            }
        }
        __syncthreads();
    }
}

// ---------------- launch ----------------
extern "C" void kernel_launch(void* const* d_in, const int* in_sizes, int n_in,
                              void* d_out, int out_size) {
    const float* x      = (const float*)d_in[0];
    const float* x_s    = (const float*)d_in[1];
    const int*   eidx   = (const int*)d_in[2];
    const float* efeat  = (const float*)d_in[3];
    const float* att_w1 = (const float*)d_in[4];
    const float* att_b1 = (const float*)d_in[5];
    const float* att_w2 = (const float*)d_in[6];
    const float* att_b2 = (const float*)d_in[7];
    const float* upd_w1 = (const float*)d_in[8];
    const float* upd_b1 = (const float*)d_in[9];
    const float* upd_w2 = (const float*)d_in[10];
    const float* upd_b2 = (const float*)d_in[11];
    float* out = (float*)d_out;

    const int PROJ_SMEM = (80 * 288 + 16 * 81) * (int)sizeof(float);
    const int UPD_SMEM  = (128 * 128 + 128 * 64 + 64 * 129 + 128 * 68 + 128 + 64) * (int)sizeof(float);
    cudaFuncSetAttribute(proj_kernel, cudaFuncAttributeMaxDynamicSharedMemorySize, PROJ_SMEM);
    cudaFuncSetAttribute(update_kernel, cudaFuncAttributeMaxDynamicSharedMemorySize, UPD_SMEM);

    // CSR build
    csr_reset_kernel<<<(N_NODES + 1023) / 1024, 1024>>>();
    csr_build_kernel<<<CSR_BLOCKS, 512>>>(eidx);

    // node projections (b1 folded into Pdst)
    proj_kernel<<<296, 288, PROJ_SMEM>>>(x, x_s, att_w1, att_b1);

    // edge attention scores (float4 gathers, uniform meta, single wave)
    score_kernel<<<592, 128>>>(efeat, att_w1, att_w2, att_b2);

    // segment softmax + aggregation
    softagg_kernel<<<(N_NODES * 32 + 255) / 256, 256>>>(x);

    // update MLP
    update_kernel<<<148, 256, UPD_SMEM>>>(x, upd_w1, upd_b1, upd_w2, upd_b2, out);
}

// round 13
// speedup vs baseline: 1.5497x; 1.1047x over previous
#include <cuda_runtime.h>
#include <math.h>

#define N_NODES 50000
#define N_EDGES 800000
#define H 64
#define S 16
#define EF 16
#define ATT_W 144
#define UPD_W 128
#define CSR_BLOCKS 148
#define CSR_CH 338          // ceil(50000/148)

// ---------------- scratch (static device allocations) ----------------
// +32 pad: allows unpredicated tail loads (statics zero-initialized; pad
// never written; tail contributions multiplied by zero weights).
__device__ float g_Psrc[N_NODES * ATT_W + 32];
__device__ float g_Pdst[N_NODES * ATT_W + 32];   // includes att_b1 folded in
__device__ float g_raw[N_EDGES];            // CSR-ordered raw scores
__device__ float g_agg[N_NODES * H];
__device__ int   g_deg[N_NODES];
__device__ int   g_rowptr[N_NODES + 1];
__device__ int   g_cursor[N_NODES];
__device__ int   g_es[N_EDGES];             // CSR-ordered original edge id
__device__ int   g_ss[N_EDGES];             // CSR-ordered src
__device__ int   g_ds[N_EDGES];             // CSR-ordered dst
__device__ int   g_bsum[CSR_BLOCKS];
__device__ unsigned int g_count;

// ---------------- f32x2 packed helpers ----------------
__device__ __forceinline__ unsigned long long pk2(float lo, float hi) {
    unsigned long long r;
    asm("mov.b64 %0, {%1, %2};" : "=l"(r) : "f"(lo), "f"(hi));
    return r;
}
__device__ __forceinline__ void upk2(unsigned long long v, float& lo, float& hi) {
    asm("mov.b64 {%0, %1}, %2;" : "=f"(lo), "=f"(hi) : "l"(v));
}
__device__ __forceinline__ unsigned long long ffma2(unsigned long long a,
                                                    unsigned long long b,
                                                    unsigned long long c) {
    unsigned long long d;
    asm("fma.rn.f32x2 %0, %1, %2, %3;" : "=l"(d) : "l"(a), "l"(b), "l"(c));
    return d;
}

// ---------------- CSR: reset then fused build ----------------
__global__ void csr_reset_kernel() {
    int i = blockIdx.x * blockDim.x + threadIdx.x;
    if (i < N_NODES) { g_deg[i] = 0; g_cursor[i] = 0; }
    if (i == 0) g_count = 0u;
}

__device__ __forceinline__ void gbar(int phase) {
    __syncthreads();
    if (threadIdx.x == 0) {
        __threadfence();
        atomicAdd(&g_count, 1u);
        while (*((volatile unsigned int*)&g_count) < (unsigned)(phase * CSR_BLOCKS)) { }
        __threadfence();
    }
    __syncthreads();
}

__global__ void __launch_bounds__(512) csr_build_kernel(const int* __restrict__ ei) {
    __shared__ int ssum[512];
    __shared__ int boff[CSR_BLOCKS];
    int t = threadIdx.x;
    int gid = blockIdx.x * 512 + t;

    // phase 1: degree histogram
    for (int e = gid; e < N_EDGES; e += CSR_BLOCKS * 512)
        atomicAdd(&g_deg[ei[N_EDGES + e]], 1);
    gbar(1);

    // phase 2: per-block inclusive scan of this block's node chunk
    int nbase = blockIdx.x * CSR_CH;
    int node = nbase + t;
    int dv = 0;
    if (t < CSR_CH && node < N_NODES) dv = g_deg[node];
    ssum[t] = dv;
    __syncthreads();
    for (int off = 1; off < 512; off <<= 1) {
        int v = (t >= off) ? ssum[t - off] : 0;
        __syncthreads();
        ssum[t] += v;
        __syncthreads();
    }
    int incl = ssum[t];
    if (t == 511) g_bsum[blockIdx.x] = ssum[511];
    gbar(2);

    // phase 3: exclusive scan of block sums, write rowptr
    if (t < CSR_BLOCKS) boff[t] = g_bsum[t];
    __syncthreads();
    if (t == 0) {
        int run = 0;
        for (int b = 0; b < CSR_BLOCKS; b++) { int tmp = boff[b]; boff[b] = run; run += tmp; }
    }
    __syncthreads();
    int myoff = boff[blockIdx.x];
    if (t < CSR_CH && node < N_NODES) g_rowptr[node] = myoff + incl - dv;
    if (blockIdx.x == 0 && t == 0) g_rowptr[N_NODES] = N_EDGES;
    gbar(3);

    // phase 4: fill (CSR-ordered edge id + src + dst)
    for (int e = gid; e < N_EDGES; e += CSR_BLOCKS * 512) {
        int s = ei[e];
        int d = ei[N_EDGES + e];
        int pos = g_rowptr[d] + atomicAdd(&g_cursor[d], 1);
        g_es[pos] = e;
        g_ss[pos] = s;
        g_ds[pos] = d;
    }
}

// ---------------- node projections (register-tiled GEMM) ----------------
// b1 is folded into the Pdst half.
__global__ void proj_kernel(const float* __restrict__ x,
                            const float* __restrict__ xs,
                            const float* __restrict__ w1,
                            const float* __restrict__ b1) {
    extern __shared__ float sm[];
    float* Wt = sm;                 // [f][j]: 80 x 288
    float* Xs = Wt + 80 * 288;      // [n][f]: 16 x 81 (pad)
    __shared__ float b1s[144];
    int tid = threadIdx.x;

    for (int idx = tid; idx < 80 * 288; idx += blockDim.x) {
        int j = idx % 288, f = idx / 288;
        int jr = (j < 144) ? j : j - 144;
        int col;
        if (j < 144) col = (f < 64) ? f : 64 + f;        // x[src] | xs[src]
        else         col = (f < 64) ? 64 + f : 80 + f;   // x[dst] | xs[dst]
        Wt[f * 288 + j] = w1[jr * 176 + col];
    }
    if (tid < 144) b1s[tid] = b1[tid];
    __syncthreads();

    int tj = tid >> 3;      // 0..35
    int tn = tid & 7;       // 0..7
    const int NCH = N_NODES / 16;   // 3125 exact

    for (int c = blockIdx.x; c < NCH; c += gridDim.x) {
        int n0 = c * 16;
        for (int idx = tid; idx < 16 * 80; idx += blockDim.x) {
            int n = idx / 80, f = idx % 80;
            int nd = n0 + n;
            Xs[n * 81 + f] = (f < 64) ? x[nd * 64 + f] : xs[nd * 16 + (f - 64)];
        }
        __syncthreads();

        float acc[8][2];
#pragma unroll
        for (int jj = 0; jj < 8; jj++) { acc[jj][0] = 0.f; acc[jj][1] = 0.f; }

        for (int f = 0; f < 80; f++) {
            float4 w0 = *(const float4*)&Wt[f * 288 + tj * 8];
            float4 w1v = *(const float4*)&Wt[f * 288 + tj * 8 + 4];
            float x0 = Xs[(tn * 2 + 0) * 81 + f];
            float x1 = Xs[(tn * 2 + 1) * 81 + f];
            float wv[8] = {w0.x, w0.y, w0.z, w0.w, w1v.x, w1v.y, w1v.z, w1v.w};
#pragma unroll
            for (int jj = 0; jj < 8; jj++) {
                acc[jj][0] = fmaf(wv[jj], x0, acc[jj][0]);
                acc[jj][1] = fmaf(wv[jj], x1, acc[jj][1]);
            }
        }

#pragma unroll
        for (int u = 0; u < 2; u++) {
            int nd = n0 + tn * 2 + u;
            int j = tj * 8;
            if (j < 144) {
                float4 o0 = {acc[0][u], acc[1][u], acc[2][u], acc[3][u]};
                float4 o1 = {acc[4][u], acc[5][u], acc[6][u], acc[7][u]};
                *(float4*)&g_Psrc[nd * 144 + j] = o0;
                *(float4*)&g_Psrc[nd * 144 + j + 4] = o1;
            } else {
                int jb = j - 144;
                float4 o0 = {acc[0][u] + b1s[jb + 0], acc[1][u] + b1s[jb + 1],
                             acc[2][u] + b1s[jb + 2], acc[3][u] + b1s[jb + 3]};
                float4 o1 = {acc[4][u] + b1s[jb + 4], acc[5][u] + b1s[jb + 5],
                             acc[6][u] + b1s[jb + 6], acc[7][u] + b1s[jb + 7]};
                *(float4*)&g_Pdst[nd * 144 + jb] = o0;
                *(float4*)&g_Pdst[nd * 144 + jb + 4] = o1;
            }
        }
        __syncthreads();
    }
}

// ---------------- edge score kernel: smem ef staging + ps/pd prefetch ---------
// Lane owns j = 4*lane..4*lane+3 plus tail j = 128+lane (lane<16).
// Chunk prologue: each lane stages its OWN edge's 64B ef row into smem once.
// t-loop: ef via broadcast LDS; next iteration's ps/pd gathers issued before
// current iteration's FFMA2 block (1-deep prefetch). Transpose-sum per 32 edges.
__global__ void __launch_bounds__(128, 4) score_kernel(
        const float* __restrict__ ef,
        const float* __restrict__ w1,
        const float* __restrict__ w2, const float* __restrict__ b2) {
    __shared__ float part[4][32 * 33];
    __shared__ __align__(16) float efs[4][32][20];   // 80B rows: 16B-aligned
    int tid = threadIdx.x;
    int lane = tid & 31;
    int wip = tid >> 5;
    float* myPart = part[wip];
    float (*myEfs)[20] = efs[wip];

    // weights: main j = 4*lane+jj, tail j = 128+lane (zeroed for lane>=16)
    unsigned long long wP[8][4];
    unsigned long long wT[8];
    float w2r[4], w2t;
#pragma unroll
    for (int jj = 0; jj < 4; jj++) {
        int j = 4 * lane + jj;              // 0..127, always valid
        w2r[jj] = w2[j];
#pragma unroll
        for (int fp = 0; fp < 8; fp++)
            wP[fp][jj] = pk2(w1[j * 176 + 160 + 2 * fp], w1[j * 176 + 160 + 2 * fp + 1]);
    }
    {
        int j = 128 + lane;
        bool v = (lane < 16);               // j<144
        w2t = v ? w2[j] : 0.f;
#pragma unroll
        for (int fp = 0; fp < 8; fp++) {
            float wlo = v ? w1[j * 176 + 160 + 2 * fp] : 0.f;
            float whi = v ? w1[j * 176 + 160 + 2 * fp + 1] : 0.f;
            wT[fp] = pk2(wlo, whi);
        }
    }
    float b2v = b2[0];

    int gw = (blockIdx.x * blockDim.x + tid) >> 5;
    int nw = (gridDim.x * blockDim.x) >> 5;
    int chunk = (N_EDGES + nw - 1) / nw;
    int p0 = gw * chunk;
    int p1 = min(p0 + chunk, N_EDGES);

    for (int cb = p0; cb < p1; cb += 32) {
        int cd = min(32, p1 - cb);      // warp-uniform

        // ---- stage ef rows into smem (one pass per chunk) ----
        {
            int eL = g_es[cb + ((lane < cd) ? lane : 0)];
            const float4* src = (const float4*)(ef + (size_t)eL * 16);
            float4 v0 = src[0], v1 = src[1], v2 = src[2], v3 = src[3];
            *(float4*)&myEfs[lane][0]  = v0;
            *(float4*)&myEfs[lane][4]  = v1;
            *(float4*)&myEfs[lane][8]  = v2;
            *(float4*)&myEfs[lane][12] = v3;
        }
        __syncwarp();

        // ---- prefetch t=0 gathers ----
        float4 ps4, pd4; float pst, pdt;
        {
            int s = g_ss[cb], d = g_ds[cb];
            const float* psrow = &g_Psrc[(size_t)s * 144];
            const float* pdrow = &g_Pdst[(size_t)d * 144];
            ps4 = *(const float4*)&psrow[4 * lane];
            pd4 = *(const float4*)&pdrow[4 * lane];
            pst = psrow[128 + lane];
            pdt = pdrow[128 + lane];
        }

        for (int t = 0; t < cd; t++) {
            // consume current
            float4 cps = ps4, cpd = pd4;
            float cpst = pst, cpdt = pdt;

            // issue next iteration's gathers before the FFMA2 block
            if (t + 1 < cd) {
                int s = g_ss[cb + t + 1], d = g_ds[cb + t + 1];
                const float* psrow = &g_Psrc[(size_t)s * 144];
                const float* pdrow = &g_Pdst[(size_t)d * 144];
                ps4 = *(const float4*)&psrow[4 * lane];
                pd4 = *(const float4*)&pdrow[4 * lane];
                pst = psrow[128 + lane];
                pdt = pdrow[128 + lane];
            }

            // ef from smem (broadcast, conflict-free)
            const float4* er = (const float4*)&myEfs[t][0];
            float4 e0 = er[0], e1 = er[1], e2 = er[2], e3 = er[3];
            unsigned long long efp[8];
            efp[0] = pk2(e0.x, e0.y); efp[1] = pk2(e0.z, e0.w);
            efp[2] = pk2(e1.x, e1.y); efp[3] = pk2(e1.z, e1.w);
            efp[4] = pk2(e2.x, e2.y); efp[5] = pk2(e2.z, e2.w);
            efp[6] = pk2(e3.x, e3.y); efp[7] = pk2(e3.z, e3.w);

            // acc = (ps, pd) packed; lo+hi at the end gives ps+pd+c (b1 in Pdst)
            unsigned long long a0 = pk2(cps.x, cpd.x);
            unsigned long long a1 = pk2(cps.y, cpd.y);
            unsigned long long a2 = pk2(cps.z, cpd.z);
            unsigned long long a3 = pk2(cps.w, cpd.w);
            unsigned long long aT = pk2(cpst, cpdt);
#pragma unroll
            for (int fp = 0; fp < 8; fp++) {
                unsigned long long v = efp[fp];
                a0 = ffma2(v, wP[fp][0], a0);
                a1 = ffma2(v, wP[fp][1], a1);
                a2 = ffma2(v, wP[fp][2], a2);
                a3 = ffma2(v, wP[fp][3], a3);
                aT = ffma2(v, wT[fp], aT);
            }
            float lo, hi, pr;
            upk2(a0, lo, hi); pr = fmaxf(lo + hi, 0.f) * w2r[0];
            upk2(a1, lo, hi); pr = fmaf(fmaxf(lo + hi, 0.f), w2r[1], pr);
            upk2(a2, lo, hi); pr = fmaf(fmaxf(lo + hi, 0.f), w2r[2], pr);
            upk2(a3, lo, hi); pr = fmaf(fmaxf(lo + hi, 0.f), w2r[3], pr);
            upk2(aT, lo, hi); pr = fmaf(fmaxf(lo + hi, 0.f), w2t,   pr);

            myPart[t * 33 + lane] = pr;   // STS ends the chain
        }
        __syncwarp();

        // transpose-sum: lane t sums row t (conflict-free: bank=(t+i)&31)
        if (lane < cd) {
            const float* row = &myPart[lane * 33];
            float s0 = 0.f, s1 = 0.f, s2 = 0.f, s3 = 0.f;
#pragma unroll
            for (int i = 0; i < 32; i += 4) {
                s0 += row[i + 0];
                s1 += row[i + 1];
                s2 += row[i + 2];
                s3 += row[i + 3];
            }
            float r = (s0 + s1) + (s2 + s3) + b2v;
            r = (r > 0.f) ? r : 0.01f * r;   // leaky_relu
            g_raw[cb + lane] = r;            // coalesced
        }
        __syncwarp();
    }
}

// ---------------- segment softmax + weighted aggregation ----------------
__global__ void softagg_kernel(const float* __restrict__ x) {
    int warp = (blockIdx.x * blockDim.x + threadIdx.x) >> 5;
    int lane = threadIdx.x & 31;
    if (warp >= N_NODES) return;
    int start = g_rowptr[warp];
    int deg = g_rowptr[warp + 1] - start;

    float m = -1e30f;
    for (int i = lane; i < deg; i += 32) m = fmaxf(m, g_raw[start + i]);
#pragma unroll
    for (int o = 16; o; o >>= 1) m = fmaxf(m, __shfl_xor_sync(0xffffffffu, m, o));

    float acc0 = 0.f, acc1 = 0.f, ws = 0.f;
    for (int base = 0; base < deg; base += 32) {
        int i = base + lane;
        float w = (i < deg) ? __expf(g_raw[start + i] - m) : 0.f;
        int sv = (i < deg) ? g_ss[start + i] : 0;
        ws += w;
        int cnt = min(32, deg - base);
        for (int t = 0; t < cnt; t++) {
            float wt = __shfl_sync(0xffffffffu, w, t);
            int st = __shfl_sync(0xffffffffu, sv, t);
            acc0 = fmaf(wt, x[(size_t)st * 64 + lane], acc0);
            acc1 = fmaf(wt, x[(size_t)st * 64 + 32 + lane], acc1);
        }
    }
#pragma unroll
    for (int o = 16; o; o >>= 1) ws += __shfl_xor_sync(0xffffffffu, ws, o);
    float scale = 1.f / (ws + 1e-9f);
    g_agg[warp * 64 + lane] = acc0 * scale;
    g_agg[warp * 64 + 32 + lane] = acc1 * scale;
}

// ---------------- fused 2-layer update MLP (register-tiled) ----------------
__global__ void update_kernel(const float* __restrict__ x,
                              const float* __restrict__ w1,
                              const float* __restrict__ b1,
                              const float* __restrict__ w2,
                              const float* __restrict__ b2,
                              float* __restrict__ out) {
    extern __shared__ float sm[];
    float* W1t = sm;                    // [f][j]: 128 x 128
    float* W2t = W1t + 128 * 128;       // [j][o]: 128 x 64
    float* Xs  = W2t + 128 * 64;        // [n][f]: 64 x 129
    float* Hs  = Xs + 64 * 129;         // [j][n]: 128 x 68
    float* b1s = Hs + 128 * 68;         // 128
    float* b2s = b1s + 128;             // 64
    int tid = threadIdx.x;

    for (int idx = tid; idx < 128 * 128; idx += 256) {
        int j = idx >> 7, f = idx & 127;
        W1t[f * 128 + j] = w1[idx];
    }
    for (int idx = tid; idx < 64 * 128; idx += 256) {
        int o = idx >> 7, j = idx & 127;
        W2t[j * 64 + o] = w2[idx];
    }
    if (tid < 128) b1s[tid] = b1[tid];
    if (tid < 64) b2s[tid] = b2[tid];
    __syncthreads();

    int tn = tid & 15;
    int tj = tid >> 4;
    const int NCH = (N_NODES + 63) / 64;

    for (int c = blockIdx.x; c < NCH; c += gridDim.x) {
        int n0 = c * 64;
        for (int idx = tid; idx < 64 * 128; idx += 256) {
            int n = idx >> 7, f = idx & 127;
            int nd = n0 + n;
            float v = 0.f;
            if (nd < N_NODES)
                v = (f < 64) ? x[nd * 64 + f] : g_agg[nd * 64 + (f - 64)];
            Xs[n * 129 + f] = v;
        }
        __syncthreads();

        {   // stage 1
            float acc[8][4];
#pragma unroll
            for (int jj = 0; jj < 8; jj++)
#pragma unroll
                for (int nn = 0; nn < 4; nn++) acc[jj][nn] = 0.f;

            for (int f = 0; f < 128; f++) {
                float4 w0 = *(const float4*)&W1t[f * 128 + tj * 8];
                float4 w1v = *(const float4*)&W1t[f * 128 + tj * 8 + 4];
                float wv[8] = {w0.x, w0.y, w0.z, w0.w, w1v.x, w1v.y, w1v.z, w1v.w};
                float xv[4];
#pragma unroll
                for (int nn = 0; nn < 4; nn++) xv[nn] = Xs[(tn * 4 + nn) * 129 + f];
#pragma unroll
                for (int jj = 0; jj < 8; jj++)
#pragma unroll
                    for (int nn = 0; nn < 4; nn++)
                        acc[jj][nn] = fmaf(wv[jj], xv[nn], acc[jj][nn]);
            }
#pragma unroll
            for (int jj = 0; jj < 8; jj++) {
                float b = b1s[tj * 8 + jj];
                float4 hv = {fmaxf(acc[jj][0] + b, 0.f), fmaxf(acc[jj][1] + b, 0.f),
                             fmaxf(acc[jj][2] + b, 0.f), fmaxf(acc[jj][3] + b, 0.f)};
                *(float4*)&Hs[(tj * 8 + jj) * 68 + tn * 4] = hv;
            }
        }
        __syncthreads();

        {   // stage 2
            int to = tid & 15;
            int tn2 = tid >> 4;
            float acc2[4][4];
#pragma unroll
            for (int nn = 0; nn < 4; nn++)
#pragma unroll
                for (int oo = 0; oo < 4; oo++) acc2[nn][oo] = 0.f;

            for (int j = 0; j < 128; j++) {
                float4 wv = *(const float4*)&W2t[j * 64 + to * 4];
                float4 hv = *(const float4*)&Hs[j * 68 + tn2 * 4];
                float h[4] = {hv.x, hv.y, hv.z, hv.w};
                float w[4] = {wv.x, wv.y, wv.z, wv.w};
#pragma unroll
                for (int nn = 0; nn < 4; nn++)
#pragma unroll
                    for (int oo = 0; oo < 4; oo++)
                        acc2[nn][oo] = fmaf(w[oo], h[nn], acc2[nn][oo]);
            }
#pragma unroll
            for (int nn = 0; nn < 4; nn++) {
                int nd = n0 + tn2 * 4 + nn;
                if (nd < N_NODES) {
                    float4 ov = {fmaxf(acc2[nn][0] + b2s[to * 4 + 0], 0.f),
                                 fmaxf(acc2[nn][1] + b2s[to * 4 + 1], 0.f),
                                 fmaxf(acc2[nn][2] + b2s[to * 4 + 2], 0.f),
                                 fmaxf(acc2[nn][3] + b2s[to * 4 + 3], 0.f)};
                    *(float4*)&out[nd * 64 + to * 4] = ov;
                }
            }
        }
        __syncthreads();
    }
}

// ---------------- launch ----------------
extern "C" void kernel_launch(void* const* d_in, const int* in_sizes, int n_in,
                              void* d_out, int out_size) {
    const float* x      = (const float*)d_in[0];
    const float* x_s    = (const float*)d_in[1];
    const int*   eidx   = (const int*)d_in[2];
    const float* efeat  = (const float*)d_in[3];
    const float* att_w1 = (const float*)d_in[4];
    const float* att_b1 = (const float*)d_in[5];
    const float* att_w2 = (const float*)d_in[6];
    const float* att_b2 = (const float*)d_in[7];
    const float* upd_w1 = (const float*)d_in[8];
    const float* upd_b1 = (const float*)d_in[9];
    const float* upd_w2 = (const float*)d_in[10];
    const float* upd_b2 = (const float*)d_in[11];
    float* out = (float*)d_out;

    const int PROJ_SMEM = (80 * 288 + 16 * 81) * (int)sizeof(float);
    const int UPD_SMEM  = (128 * 128 + 128 * 64 + 64 * 129 + 128 * 68 + 128 + 64) * (int)sizeof(float);
    cudaFuncSetAttribute(proj_kernel, cudaFuncAttributeMaxDynamicSharedMemorySize, PROJ_SMEM);
    cudaFuncSetAttribute(update_kernel, cudaFuncAttributeMaxDynamicSharedMemorySize, UPD_SMEM);

    // CSR build
    csr_reset_kernel<<<(N_NODES + 1023) / 1024, 1024>>>();
    csr_build_kernel<<<CSR_BLOCKS, 512>>>(eidx);

    // node projections (b1 folded into Pdst)
    proj_kernel<<<296, 288, PROJ_SMEM>>>(x, x_s, att_w1, att_b1);

    // edge attention scores (smem ef staging + ps/pd prefetch, single wave)
    score_kernel<<<592, 128>>>(efeat, att_w1, att_w2, att_b2);

    // segment softmax + aggregation
    softagg_kernel<<<(N_NODES * 32 + 255) / 256, 256>>>(x);

    // update MLP
    update_kernel<<<148, 256, UPD_SMEM>>>(x, upd_w1, upd_b1, upd_w2, upd_b2, out);
}